// round 14
// baseline (speedup 1.0000x reference)
#include <cuda_runtime.h>
#include <cuda_bf16.h>
#include <cuda_fp16.h>
#include <cstdint>
#include <cstdio>

// ---------------------------------------------------------------------------
// Problem constants
// ---------------------------------------------------------------------------
#define D_MODEL   2048
#define NUM_HEADS 16
#define HEAD_DIM  128
#define BATCH     4
#define TQ        1024
#define CACHE_LEN 1024
#define M_ROWS    (BATCH * TQ)          // 4096

// scratch (device globals: allocation-free scratch per harness rules)
__device__ __half g_hQ[M_ROWS * D_MODEL];             // projected Q, fp16
__device__ __half g_O[M_ROWS * D_MODEL];              // attention out, fp16
// fp16 pre-rounded inputs
__device__ __half g_hq[M_ROWS * D_MODEL];
__device__ __half g_hk[M_ROWS * D_MODEL];
__device__ __half g_hv[M_ROWS * D_MODEL];
__device__ __half g_hWq[D_MODEL * D_MODEL];
__device__ __half g_hWk[D_MODEL * D_MODEL];
__device__ __half g_hWv[D_MODEL * D_MODEL];
__device__ __half g_hWo[D_MODEL * D_MODEL];
__device__ __half g_hck[BATCH * CACHE_LEN * D_MODEL]; // fp16 cache K (attention)
__device__ __half g_hcv[BATCH * CACHE_LEN * D_MODEL]; // fp16 cache V (attention)

// ---------------------------------------------------------------------------
// helpers
// ---------------------------------------------------------------------------
__device__ __forceinline__ uint32_t smem_u32(const void* p) {
    uint32_t a;
    asm("{ .reg .u64 t; cvta.to.shared.u64 t, %1; cvt.u32.u64 %0, t; }"
        : "=r"(a) : "l"(p));
    return a;
}

// fp16 m16n8k16: D += A*B  (row.col, f32 accum)
__device__ __forceinline__ void mma_f16(float* d, const uint32_t* a, const uint32_t* b) {
    asm volatile(
        "mma.sync.aligned.m16n8k16.row.col.f32.f16.f16.f32 "
        "{%0,%1,%2,%3}, {%4,%5,%6,%7}, {%8,%9}, {%0,%1,%2,%3};\n"
        : "+f"(d[0]), "+f"(d[1]), "+f"(d[2]), "+f"(d[3])
        : "r"(a[0]), "r"(a[1]), "r"(a[2]), "r"(a[3]),
          "r"(b[0]), "r"(b[1]));
}

__device__ __forceinline__ void ldsm_x4(uint32_t* r, uint32_t addr) {
    asm volatile("ldmatrix.sync.aligned.m8n8.x4.shared.b16 {%0,%1,%2,%3}, [%4];"
                 : "=r"(r[0]), "=r"(r[1]), "=r"(r[2]), "=r"(r[3]) : "r"(addr));
}

__device__ __forceinline__ void ldsm_x4t(uint32_t* r, uint32_t addr) {
    asm volatile("ldmatrix.sync.aligned.m8n8.x4.trans.shared.b16 {%0,%1,%2,%3}, [%4];"
                 : "=r"(r[0]), "=r"(r[1]), "=r"(r[2]), "=r"(r[3]) : "r"(addr));
}

// packed half2 2^x (one MUFU op for two values)
__device__ __forceinline__ uint32_t h2exp2_(uint32_t x) {
    uint32_t r;
    asm("ex2.approx.f16x2 %0, %1;" : "=r"(r) : "r"(x));
    return r;
}

__device__ __forceinline__ void cp_async16(uint32_t dst, const void* src) {
    asm volatile("cp.async.cg.shared.global [%0], [%1], 16;"
                 :: "r"(dst), "l"(src));
}
#define CP_COMMIT()  asm volatile("cp.async.commit_group;" ::: "memory")
#define CP_WAIT(N)   asm volatile("cp.async.wait_group %0;" :: "n"(N) : "memory")

// ---------------------------------------------------------------------------
// pre-rounding pass: dst = fp16(src), up to 7 tensors per launch (grid.z)
// ---------------------------------------------------------------------------
struct RoundArgs {
    const float* src[7];
    __half*      dst[7];
    int          n4[7];     // number of float4 elements
};

__global__ __launch_bounds__(256) void round_f16(RoundArgs ra) {
    const int z = blockIdx.z;
    const int i = blockIdx.x * 256 + threadIdx.x;
    if (i >= ra.n4[z]) return;
    float4 v = ((const float4*)ra.src[z])[i];
    __half2 h0 = __floats2half2_rn(v.x, v.y);
    __half2 h1 = __floats2half2_rn(v.z, v.w);
    uint2 u;
    u.x = *(uint32_t*)&h0;
    u.y = *(uint32_t*)&h1;
    ((uint2*)ra.dst[z])[i] = u;
}

// ---------------------------------------------------------------------------
// Pipelined TN GEMM (fp16 HMMA):  C[M,N] = A[M,K] * W[N,K]^T + bias[N]
// CTA 128x128 with FOUR warps (128 threads), warp tile 64x64 (2x2 grid).
// K-tile 64, 3-stage cp.async ring, m16n8k16 HMMA. (byte-identical to R13)
// Output modes: 0 = fp16 to Ch (Q-proj), 1 = permuted fp32 into new_kv
// (K/V proj land directly in d_out), 2 = plain fp32 (O-proj).
// ---------------------------------------------------------------------------
#define NST        3
#define TILE_B     16384                 // 128 rows * 128 bytes
#define GEMM_SMEM  (2 * NST * TILE_B + 1024)
#define NKT        (D_MODEL / 64)        // 32 k-tiles

struct ProjArgs {
    const __half* A[3];
    const __half* W[3];
    const float*  Bias[3];
    float*        C[3];
    __half*       Ch[3];
    int           mode[3];
};

__global__ __launch_bounds__(128, 2) void gemm_tc(ProjArgs args) {
    extern __shared__ char dyn_smem[];
    char* db = (char*)(((uintptr_t)dyn_smem + 1023) & ~(uintptr_t)1023);
    const uint32_t db_u = smem_u32(db);

    const int z = blockIdx.z;
    const __half* __restrict__ A    = args.A[z];
    const __half* __restrict__ W    = args.W[z];
    const float*  __restrict__ bias = args.Bias[z];
    float* __restrict__        C    = args.C[z];
    __half* __restrict__       Ch   = args.Ch[z];
    const int mode = args.mode[z];

    const int tid  = threadIdx.x;
    const int lane = tid & 31;
    const int w    = tid >> 5;     // 0..3
    const int wm   = w >> 1;       // 0..1
    const int wn   = w & 1;        // 0..1
    const int n0   = blockIdx.x * 128;
    const int m0   = blockIdx.y * 128;

    const __half* Ag = A + (size_t)m0 * D_MODEL;
    const __half* Wg = W + (size_t)n0 * D_MODEL;

    // per-thread load geometry: 8 chunks A + 8 chunks B per stage (128 thr)
    uint32_t swoff[8];
    size_t   gofs[8];
#pragma unroll
    for (int rep = 0; rep < 8; rep++) {
        const int g = rep * 128 + tid;          // 0..1023
        const int r = g >> 3;                   // row 0..127
        const int i = g & 7;                    // 16B chunk
        gofs[rep]  = (size_t)r * D_MODEL + i * 8;
        swoff[rep] = (uint32_t)((r * 128 + i * 16) ^ ((r & 7) << 4));
    }

    float acc[4][8][4];
#pragma unroll
    for (int i = 0; i < 4; i++)
#pragma unroll
        for (int j = 0; j < 8; j++)
#pragma unroll
            for (int k = 0; k < 4; k++) acc[i][j][k] = 0.f;

    auto issue = [&](int ks) {
        const int slot = ks % NST;
        const int kc   = ks * 64;
        const uint32_t da  = db_u + slot * TILE_B;
        const uint32_t dbb = db_u + NST * TILE_B + slot * TILE_B;
#pragma unroll
        for (int rep = 0; rep < 8; rep++)
            cp_async16(da + swoff[rep], Ag + gofs[rep] + kc);
#pragma unroll
        for (int rep = 0; rep < 8; rep++)
            cp_async16(dbb + swoff[rep], Wg + gofs[rep] + kc);
        CP_COMMIT();
    };

    issue(0);
    issue(1);

    const int m_ = lane >> 3;
    const int rr = lane & 7;
    const int a_row_base = wm * 64 + (m_ & 1) * 8 + rr;   // + mf*16
    const int b_row_base = wn * 64 + (m_ & 1) * 8 + rr;   // + nf2*16
    const int k_half     = (m_ >> 1) * 16;

#pragma unroll 1
    for (int kt = 0; kt < NKT; kt++) {
        if (kt < NKT - 2) { CP_WAIT(1); } else { CP_WAIT(0); }
        __syncthreads();
        if (kt + 2 < NKT) issue(kt + 2);

        const int slot = kt % NST;
        const uint32_t da  = db_u + slot * TILE_B;
        const uint32_t dbb = db_u + NST * TILE_B + slot * TILE_B;

#pragma unroll
        for (int ks = 0; ks < 4; ks++) {
            const int kb = ks * 32 + k_half;
            uint32_t a[4][4], b[8][2];
#pragma unroll
            for (int mf = 0; mf < 4; mf++) {
                const int row = a_row_base + mf * 16;
                const uint32_t off = (uint32_t)((row * 128 + kb) ^ ((row & 7) << 4));
                ldsm_x4(a[mf], da + off);
            }
#pragma unroll
            for (int nf2 = 0; nf2 < 4; nf2++) {
                const int row = b_row_base + nf2 * 16;
                const uint32_t off = (uint32_t)((row * 128 + kb) ^ ((row & 7) << 4));
                uint32_t t[4];
                ldsm_x4(t, dbb + off);
                b[nf2 * 2][0]     = t[0]; b[nf2 * 2][1]     = t[2];
                b[nf2 * 2 + 1][0] = t[1]; b[nf2 * 2 + 1][1] = t[3];
            }
#pragma unroll
            for (int mf = 0; mf < 4; mf++)
#pragma unroll
                for (int nf = 0; nf < 8; nf++)
                    mma_f16(acc[mf][nf], a[mf], b[nf]);
        }
    }

    // epilogue (per mode)
#pragma unroll
    for (int mf = 0; mf < 4; mf++) {
#pragma unroll
        for (int nf = 0; nf < 8; nf++) {
            const int row = m0 + wm * 64 + mf * 16 + (lane >> 2);
            const int col = n0 + wn * 64 + nf * 8 + (lane & 3) * 2;
            const float b0 = bias[col], b1 = bias[col + 1];
            const float x0 = acc[mf][nf][0] + b0, x1 = acc[mf][nf][1] + b1;
            const float y0 = acc[mf][nf][2] + b0, y1 = acc[mf][nf][3] + b1;
            if (mode == 0) {
                __half2 h0 = __floats2half2_rn(x0, x1);
                __half2 h1 = __floats2half2_rn(y0, y1);
                *(__half2*)&Ch[(size_t)row * D_MODEL + col]       = h0;
                *(__half2*)&Ch[(size_t)(row + 8) * D_MODEL + col] = h1;
            } else if (mode == 1) {
                // direct write into new_k/new_v (proj half): t' = 1024 + t
                const int h  = col >> 7, d = col & 127;
#pragma unroll
                for (int rep = 0; rep < 2; rep++) {
                    const int rw = row + rep * 8;
                    const int bb = rw >> 10, t = rw & 1023;
                    const int j  = h * 128 + 64 + (t >> 4);
                    const int c  = (t & 15) * 128 + d;
                    float2 v = rep ? make_float2(y0, y1) : make_float2(x0, x1);
                    *(float2*)&C[((size_t)bb * 2048 + j) * 2048 + c] = v;
                }
            } else {
                *(float2*)&C[(size_t)row * D_MODEL + col]       = make_float2(x0, x1);
                *(float2*)&C[(size_t)(row + 8) * D_MODEL + col] = make_float2(y0, y1);
            }
        }
    }
}

// ---------------------------------------------------------------------------
// fp16 flash attention over the cache only (mask tril(TQ,total) => cache half).
// 128 threads (4 warps), 64 q-rows/CTA, 64 kv/tile, fused K+V commit groups,
// single CP_WAIT + 2 barriers per iteration; P in registers; l via ones-column
// tensor-core MMA; P pairs via ex2.approx.f16x2. (byte-identical to R13)
// SMEM: Q 16K | K0 K1 32K | V0 V1 32K = 80K, 2 CTA/SM.
// qi reversed vs blockIdx.x: heavy (long) CTAs launch first -> better tail.
// ---------------------------------------------------------------------------
#define QOFF 0
#define KOFF 16384
#define VOFF (KOFF + 2 * 16384)
#define ATT_SMEM (VOFF + 2 * 16384)   // 81920

__global__ __launch_bounds__(128, 2) void attn_kernel(
    const __half* __restrict__ gQ,
    const __half* __restrict__ hK,
    const __half* __restrict__ hV,
    __half* __restrict__ gO)
{
    extern __shared__ char smc[];
    const uint32_t sb = smem_u32(smc);
    const int tid = threadIdx.x, lane = tid & 31, w = tid >> 5;
    const int qi = (int)gridDim.x - 1 - blockIdx.x;   // heavy tiles first
    const int h = blockIdx.y, b = blockIdx.z;
    const int q0 = qi * 64;

    const __half* Qg = gQ + ((size_t)b * TQ + q0) * D_MODEL + h * HEAD_DIM;
    const __half* Kg = hK + (size_t)b * CACHE_LEN * D_MODEL + h * HEAD_DIM;
    const __half* Vg = hV + (size_t)b * CACHE_LEN * D_MODEL + h * HEAD_DIM;

    // Q tile 64x128 halves -> swizzled smem (rows 256B)
#pragma unroll
    for (int rep = 0; rep < 8; rep++) {
        const int g = rep * 128 + tid;
        const int r = g >> 4, i = g & 15;
        uint4 v = *(const uint4*)(Qg + (size_t)r * D_MODEL + i * 8);
        *(uint4*)(smc + QOFF + ((r * 256 + i * 16) ^ ((r & 7) << 4))) = v;
    }

    // one commit group per kv-tile: K chunks + V chunks together
    auto issueKV = [&](int kt) {
#pragma unroll
        for (int rep = 0; rep < 8; rep++) {
            const int g = rep * 128 + tid;
            const int r = g >> 4, i = g & 15;
            const uint32_t so = (uint32_t)((r * 256 + i * 16) ^ ((r & 7) << 4));
            cp_async16(sb + KOFF + (kt & 1) * 16384 + so,
                       Kg + (size_t)(kt * 64 + r) * D_MODEL + i * 8);
            cp_async16(sb + VOFF + (kt & 1) * 16384 + so,
                       Vg + (size_t)(kt * 64 + r) * D_MODEL + i * 8);
        }
        CP_COMMIT();
    };

    issueKV(0);
    if (qi >= 1) issueKV(1); else CP_COMMIT();

    float acc_o[16][4];
#pragma unroll
    for (int i = 0; i < 16; i++)
#pragma unroll
        for (int j = 0; j < 4; j++) acc_o[i][j] = 0.f;
    float acc_l[4] = {0.f, 0.f, 0.f, 0.f};   // ones-column row-sum accumulator
    float mrow[2] = {-1e30f, -1e30f};        // running max of UNSCALED scores
    // exp(sc*(s-m)) == exp2f((s-m)*C2), C2 = (1/sqrt(128))*log2(e)
    const float C2 = (float)(0.08838834764831845 * 1.4426950408889634);

    // B-frag of all-ones in column 0 (col = lane>>2): lanes 0..3 hold 1.0h pairs
    const uint32_t b_ones = ((lane >> 2) == 0) ? 0x3C003C00u : 0u;
    uint32_t bO[2] = { b_ones, b_ones };

    const int m_ = lane >> 3, rr = lane & 7;
    const int kh    = (m_ >> 1) * 16;
    const int a_row = w * 16 + (m_ & 1) * 8 + rr;

    for (int kt = 0; kt <= qi; kt++) {
        CP_WAIT(1);            // KV(kt) landed (groups complete in order)
        __syncthreads();       // visible to all warps (covers Q on kt=0)

        const uint32_t kbase = sb + KOFF + (kt & 1) * 16384;
        float accs[8][4];
#pragma unroll
        for (int i = 0; i < 8; i++)
#pragma unroll
            for (int j = 0; j < 4; j++) accs[i][j] = 0.f;

#pragma unroll
        for (int ks = 0; ks < 8; ks++) {            // 8 x k16 over headdim 128
            const int colb = ks * 32 + kh;
            uint32_t a[4];
            ldsm_x4(a, sb + QOFF + ((a_row * 256 + colb) ^ ((a_row & 7) << 4)));
            uint32_t bfr[8][2];
#pragma unroll
            for (int nf2 = 0; nf2 < 4; nf2++) {
                const int row = nf2 * 16 + (m_ & 1) * 8 + rr;   // kv rows 0..63
                uint32_t t[4];
                ldsm_x4(t, kbase + ((row * 256 + colb) ^ ((row & 7) << 4)));
                bfr[nf2 * 2][0]     = t[0]; bfr[nf2 * 2][1]     = t[2];
                bfr[nf2 * 2 + 1][0] = t[1]; bfr[nf2 * 2 + 1][1] = t[3];
            }
#pragma unroll
            for (int nf = 0; nf < 8; nf++) mma_f16(accs[nf], a, bfr[nf]);
        }

        // causal mask (diagonal tile only) on UNSCALED scores
        if (kt == qi) {
#pragma unroll
            for (int nf = 0; nf < 8; nf++)
#pragma unroll
                for (int r = 0; r < 2; r++)
#pragma unroll
                    for (int j = 0; j < 2; j++) {
                        const int cl = nf * 8 + (lane & 3) * 2 + j;
                        const int rl = w * 16 + (lane >> 2) + r * 8;
                        if (cl > rl) accs[nf][r * 2 + j] = -1e30f;
                    }
        }

        // online softmax (scale folded into exp2; P pairs via ex2.f16x2)
        uint32_t ph[8][2];
#pragma unroll
        for (int r = 0; r < 2; r++) {
            float vmax = -1e30f;
#pragma unroll
            for (int nf = 0; nf < 8; nf++) {
                vmax = fmaxf(vmax, accs[nf][r * 2]);
                vmax = fmaxf(vmax, accs[nf][r * 2 + 1]);
            }
            vmax = fmaxf(vmax, __shfl_xor_sync(0xffffffffu, vmax, 1));
            vmax = fmaxf(vmax, __shfl_xor_sync(0xffffffffu, vmax, 2));
            const float mnew = fmaxf(mrow[r], vmax);
#pragma unroll
            for (int nf = 0; nf < 8; nf++) {
                __half2 e = __floats2half2_rn((accs[nf][r * 2]     - mnew) * C2,
                                              (accs[nf][r * 2 + 1] - mnew) * C2);
                ph[nf][r] = h2exp2_(*(uint32_t*)&e);
            }
            const float alpha = exp2f((mrow[r] - mnew) * C2);
            mrow[r] = mnew;
            acc_l[r * 2]     *= alpha;
            acc_l[r * 2 + 1] *= alpha;
#pragma unroll
            for (int nf = 0; nf < 16; nf++) {
                acc_o[nf][r * 2]     *= alpha;
                acc_o[nf][r * 2 + 1] *= alpha;
            }
        }

        // O += P * V ; l += P * 1  (V arrived with K; P A-frags from registers)
        const uint32_t vbase = sb + VOFF + (kt & 1) * 16384;
        const int vr_lane = ((lane >> 3) & 1) * 8 + (lane & 7);
        const int vc_lane = (lane >> 4) * 16;
#pragma unroll
        for (int ks = 0; ks < 4; ks++) {            // 4 x k16 over 64 kv
            uint32_t aP[4];
            aP[0] = ph[2 * ks][0];
            aP[1] = ph[2 * ks][1];
            aP[2] = ph[2 * ks + 1][0];
            aP[3] = ph[2 * ks + 1][1];
            mma_f16(acc_l, aP, bO);                 // row-sum into col 0
#pragma unroll
            for (int dg = 0; dg < 8; dg++) {        // 16 halves of headdim each
                const int vrow = ks * 16 + vr_lane;
                const int vcol = dg * 32 + vc_lane;
                uint32_t t[4];
                ldsm_x4t(t, vbase + ((vrow * 256 + vcol) ^ ((vrow & 7) << 4)));
                uint32_t b0[2] = { t[0], t[1] };
                uint32_t b1[2] = { t[2], t[3] };
                mma_f16(acc_o[dg * 2],     aP, b0);
                mma_f16(acc_o[dg * 2 + 1], aP, b1);
            }
        }

        __syncthreads();       // all warps done reading K(kt)/V(kt)
        if (kt + 2 <= qi) issueKV(kt + 2); else CP_COMMIT();
    }

    // l lives in col 0 (lanes with lane%4==0); broadcast across each quad
    const int qlead = lane & ~3;
    const float l0 = __shfl_sync(0xffffffffu, acc_l[0], qlead);
    const float l1 = __shfl_sync(0xffffffffu, acc_l[2], qlead);
    const float inv0 = 1.f / l0;
    const float inv1 = 1.f / l1;

    // normalize + write fp16
#pragma unroll
    for (int nf = 0; nf < 16; nf++)
#pragma unroll
        for (int r = 0; r < 2; r++) {
            const int row = q0 + w * 16 + (lane >> 2) + r * 8;
            const int col = h * HEAD_DIM + nf * 8 + (lane & 3) * 2;
            const float inv = r ? inv1 : inv0;
            __half2 hv = __floats2half2_rn(acc_o[nf][r * 2] * inv,
                                           acc_o[nf][r * 2 + 1] * inv);
            *(__half2*)&gO[((size_t)b * TQ + row) * D_MODEL + col] = hv;
        }
}

// ---------------------------------------------------------------------------
// cache pass, fused: permuted fp32 cache half of new_k/new_v into d_out AND
// fp16 rounding of the caches for attention (single read of each cache).
// grid.z: 0 -> K, 1 -> V. 2097152 float4 per tensor.
// ---------------------------------------------------------------------------
__global__ __launch_bounds__(256) void copy_cache_kv(
    const float* __restrict__ cacheK,
    const float* __restrict__ cacheV,
    float* __restrict__ dstK,
    float* __restrict__ dstV,
    __half* __restrict__ hcK,
    __half* __restrict__ hcV)
{
    const int i = blockIdx.x * 256 + threadIdx.x;
    const int b   = i >> 19;            // 524288 float4 per batch
    const int rem = i & 524287;
    const int jj  = rem >> 9;           // 0..1023 (h*64 + cache row)
    const int c   = (rem & 511) * 4;
    const int h   = jj >> 6;
    const int j   = h * 128 + (jj & 63);
    const int t   = (jj & 63) * 16 + (c >> 7);
    const int d   = c & 127;

    const float* cache = blockIdx.z ? cacheV : cacheK;
    float*       dst   = blockIdx.z ? dstV   : dstK;
    __half*      hc    = blockIdx.z ? hcV    : hcK;

    const size_t src_off = ((size_t)b * CACHE_LEN + t) * D_MODEL + h * HEAD_DIM + d;
    float4 v = *(const float4*)&cache[src_off];
    *(float4*)&dst[((size_t)b * 2048 + j) * D_MODEL + c] = v;

    __half2 h0 = __floats2half2_rn(v.x, v.y);
    __half2 h1 = __floats2half2_rn(v.z, v.w);
    uint2 u;
    u.x = *(uint32_t*)&h0;
    u.y = *(uint32_t*)&h1;
    *(uint2*)&hc[src_off] = u;
}

// ---------------------------------------------------------------------------
// launch — three-branch DAG (all kernels byte-identical to R13):
//   s3 (t=0):              cache pass -> evC
//   s2 (t=0, high prio):   round(k,v,Wk,Wv) -> K/V-proj -> evK
//   s0:                    round(q,Wq,Wo) -> Q-proj -> [evC] attn -> O-proj
//                          -> [evK]
// K/V-proj (the long pole) now starts ~25us earlier; the three t=0 memory
// passes share DRAM concurrently instead of serializing inside one stream.
// ---------------------------------------------------------------------------
extern "C" void kernel_launch(void* const* d_in, const int* in_sizes, int n_in,
                              void* d_out, int out_size)
{
    const float* query   = (const float*)d_in[0];
    const float* key     = (const float*)d_in[1];
    const float* value   = (const float*)d_in[2];
    const float* cacheK  = (const float*)d_in[3];
    const float* cacheV  = (const float*)d_in[4];
    const float* Wq      = (const float*)d_in[5];
    const float* bq      = (const float*)d_in[6];
    const float* Wk      = (const float*)d_in[7];
    const float* bk      = (const float*)d_in[8];
    const float* Wv      = (const float*)d_in[9];
    const float* bv      = (const float*)d_in[10];
    const float* Wo      = (const float*)d_in[11];
    const float* bo      = (const float*)d_in[12];
    float* out = (float*)d_out;

    __half *phQ, *pO, *phq, *phk, *phv, *phWq, *phWk, *phWv, *phWo, *phck, *phcv;
    cudaGetSymbolAddress((void**)&phQ, g_hQ);
    cudaGetSymbolAddress((void**)&pO, g_O);
    cudaGetSymbolAddress((void**)&phq, g_hq);
    cudaGetSymbolAddress((void**)&phk, g_hk);
    cudaGetSymbolAddress((void**)&phv, g_hv);
    cudaGetSymbolAddress((void**)&phWq, g_hWq);
    cudaGetSymbolAddress((void**)&phWk, g_hWk);
    cudaGetSymbolAddress((void**)&phWv, g_hWv);
    cudaGetSymbolAddress((void**)&phWo, g_hWo);
    cudaGetSymbolAddress((void**)&phck, g_hck);
    cudaGetSymbolAddress((void**)&phcv, g_hcv);

    // one-time stream/event creation (resources only; identical work per call)
    static cudaStream_t s2 = nullptr, s3 = nullptr;
    static cudaEvent_t  evF = nullptr, evC = nullptr, evK = nullptr;
    if (s2 == nullptr) {
        int loPrio = 0, hiPrio = 0;
        cudaDeviceGetStreamPriorityRange(&loPrio, &hiPrio);
        cudaStreamCreateWithPriority(&s2, cudaStreamNonBlocking, hiPrio);
        cudaStreamCreateWithFlags(&s3, cudaStreamNonBlocking);
        cudaEventCreateWithFlags(&evF, cudaEventDisableTiming);
        cudaEventCreateWithFlags(&evC, cudaEventDisableTiming);
        cudaEventCreateWithFlags(&evK, cudaEventDisableTiming);
    }

    cudaFuncSetAttribute(gemm_tc, cudaFuncAttributeMaxDynamicSharedMemorySize,
                         GEMM_SMEM);
    cudaFuncSetAttribute(attn_kernel, cudaFuncAttributeMaxDynamicSharedMemorySize,
                         ATT_SMEM);

    const int NA = M_ROWS * D_MODEL / 4;     // 2097152 float4
    const int NW = D_MODEL * D_MODEL / 4;    // 1048576 float4

    // fork both side streams at t=0
    cudaEventRecord(evF, 0);
    cudaStreamWaitEvent(s2, evF, 0);
    cudaStreamWaitEvent(s3, evF, 0);

    // ---- s3: cache pass (only attention depends on it) ----
    copy_cache_kv<<<dim3(2097152 / 256, 1, 2), 256, 0, s3>>>(
        cacheK, cacheV, out + 8388608, out + 25165824, phck, phcv);
    cudaEventRecord(evC, s3);

    // ---- s2 (high priority): K/V branch ----
    RoundArgs rb;
    rb.src[0] = key;   rb.dst[0] = phk;  rb.n4[0] = NA;
    rb.src[1] = value; rb.dst[1] = phv;  rb.n4[1] = NA;
    rb.src[2] = Wk;    rb.dst[2] = phWk; rb.n4[2] = NW;
    rb.src[3] = Wv;    rb.dst[3] = phWv; rb.n4[3] = NW;
    for (int s = 4; s < 7; s++) { rb.src[s] = Wv; rb.dst[s] = phWv; rb.n4[s] = 0; }
    round_f16<<<dim3(NA / 256, 1, 4), 256, 0, s2>>>(rb);

    ProjArgs pkv;
    pkv.A[0] = phk; pkv.W[0] = phWk; pkv.Bias[0] = bk;
    pkv.C[0] = out + 8388608;  pkv.Ch[0] = nullptr; pkv.mode[0] = 1;
    pkv.A[1] = phv; pkv.W[1] = phWv; pkv.Bias[1] = bv;
    pkv.C[1] = out + 25165824; pkv.Ch[1] = nullptr; pkv.mode[1] = 1;
    pkv.A[2] = pkv.A[0]; pkv.W[2] = pkv.W[0]; pkv.Bias[2] = pkv.Bias[0];
    pkv.C[2] = pkv.C[0]; pkv.Ch[2] = nullptr; pkv.mode[2] = 1;
    gemm_tc<<<dim3(D_MODEL / 128, M_ROWS / 128, 2), 128, GEMM_SMEM, s2>>>(pkv);
    cudaEventRecord(evK, s2);

    // ---- s0: attention chain ----
    RoundArgs raA;
    raA.src[0] = query; raA.dst[0] = phq;  raA.n4[0] = NA;
    raA.src[1] = Wq;    raA.dst[1] = phWq; raA.n4[1] = NW;
    raA.src[2] = Wo;    raA.dst[2] = phWo; raA.n4[2] = NW;
    for (int s = 3; s < 7; s++) { raA.src[s] = Wo; raA.dst[s] = phWo; raA.n4[s] = 0; }
    round_f16<<<dim3(NA / 256, 1, 3), 256>>>(raA);

    ProjArgs pq;
    pq.A[0] = phq; pq.W[0] = phWq; pq.Bias[0] = bq;
    pq.C[0] = nullptr; pq.Ch[0] = phQ; pq.mode[0] = 0;
    pq.A[1] = pq.A[0]; pq.W[1] = pq.W[0]; pq.Bias[1] = pq.Bias[0];
    pq.C[1] = nullptr; pq.Ch[1] = phQ; pq.mode[1] = 0;
    pq.A[2] = pq.A[0]; pq.W[2] = pq.W[0]; pq.Bias[2] = pq.Bias[0];
    pq.C[2] = nullptr; pq.Ch[2] = phQ; pq.mode[2] = 0;
    gemm_tc<<<dim3(D_MODEL / 128, M_ROWS / 128, 1), 128, GEMM_SMEM>>>(pq);

    // attention needs the fp16 caches from s3's cache pass
    cudaStreamWaitEvent(0, evC, 0);
    attn_kernel<<<dim3(TQ / 64, NUM_HEADS, BATCH), 128, ATT_SMEM>>>(
        phQ, phck, phcv, pO);

    // O-projection -> out[0 .. 8388608)  (co-runs with K/V-proj tail)
    ProjArgs po;
    po.A[0] = pO; po.W[0] = phWo; po.Bias[0] = bo;
    po.C[0] = out; po.Ch[0] = nullptr; po.mode[0] = 2;
    po.A[1] = po.A[0]; po.W[1] = po.W[0]; po.Bias[1] = po.Bias[0];
    po.C[1] = po.C[0]; po.Ch[1] = nullptr; po.mode[1] = 2;
    po.A[2] = po.A[0]; po.W[2] = po.W[0]; po.Bias[2] = po.Bias[0];
    po.C[2] = po.C[0]; po.Ch[2] = nullptr; po.mode[2] = 2;
    gemm_tc<<<dim3(D_MODEL / 128, M_ROWS / 128, 1), 128, GEMM_SMEM>>>(po);

    // join
    cudaStreamWaitEvent(0, evK, 0);
}

// round 15
// speedup vs baseline: 1.0099x; 1.0099x over previous
#include <cuda_runtime.h>
#include <cuda_bf16.h>
#include <cuda_fp16.h>
#include <cstdint>
#include <cstdio>

// ---------------------------------------------------------------------------
// Problem constants
// ---------------------------------------------------------------------------
#define D_MODEL   2048
#define NUM_HEADS 16
#define HEAD_DIM  128
#define BATCH     4
#define TQ        1024
#define CACHE_LEN 1024
#define M_ROWS    (BATCH * TQ)          // 4096

// scratch (device globals: allocation-free scratch per harness rules)
__device__ __half g_hQ[M_ROWS * D_MODEL];             // projected Q, fp16
__device__ __half g_O[M_ROWS * D_MODEL];              // attention out, fp16
// fp16 pre-rounded inputs
__device__ __half g_hq[M_ROWS * D_MODEL];
__device__ __half g_hk[M_ROWS * D_MODEL];
__device__ __half g_hv[M_ROWS * D_MODEL];
__device__ __half g_hWq[D_MODEL * D_MODEL];
__device__ __half g_hWk[D_MODEL * D_MODEL];
__device__ __half g_hWv[D_MODEL * D_MODEL];
__device__ __half g_hWo[D_MODEL * D_MODEL];
__device__ __half g_hck[BATCH * CACHE_LEN * D_MODEL]; // fp16 cache K (attention)
__device__ __half g_hcv[BATCH * CACHE_LEN * D_MODEL]; // fp16 cache V (attention)

// ---------------------------------------------------------------------------
// helpers
// ---------------------------------------------------------------------------
__device__ __forceinline__ uint32_t smem_u32(const void* p) {
    uint32_t a;
    asm("{ .reg .u64 t; cvta.to.shared.u64 t, %1; cvt.u32.u64 %0, t; }"
        : "=r"(a) : "l"(p));
    return a;
}

// fp16 m16n8k16: D += A*B  (row.col, f32 accum)
__device__ __forceinline__ void mma_f16(float* d, const uint32_t* a, const uint32_t* b) {
    asm volatile(
        "mma.sync.aligned.m16n8k16.row.col.f32.f16.f16.f32 "
        "{%0,%1,%2,%3}, {%4,%5,%6,%7}, {%8,%9}, {%0,%1,%2,%3};\n"
        : "+f"(d[0]), "+f"(d[1]), "+f"(d[2]), "+f"(d[3])
        : "r"(a[0]), "r"(a[1]), "r"(a[2]), "r"(a[3]),
          "r"(b[0]), "r"(b[1]));
}

// fp16 m16n8k16 with fp16 accumulator (D/C packed half2 x2) — used for the
// attention S-matmul to probe whether f16-acc HMMA runs at 2x on sm_103a.
__device__ __forceinline__ void mma_f16acc(uint32_t* d, const uint32_t* a, const uint32_t* b) {
    asm volatile(
        "mma.sync.aligned.m16n8k16.row.col.f16.f16.f16.f16 "
        "{%0,%1}, {%2,%3,%4,%5}, {%6,%7}, {%0,%1};\n"
        : "+r"(d[0]), "+r"(d[1])
        : "r"(a[0]), "r"(a[1]), "r"(a[2]), "r"(a[3]),
          "r"(b[0]), "r"(b[1]));
}

__device__ __forceinline__ void ldsm_x4(uint32_t* r, uint32_t addr) {
    asm volatile("ldmatrix.sync.aligned.m8n8.x4.shared.b16 {%0,%1,%2,%3}, [%4];"
                 : "=r"(r[0]), "=r"(r[1]), "=r"(r[2]), "=r"(r[3]) : "r"(addr));
}

__device__ __forceinline__ void ldsm_x4t(uint32_t* r, uint32_t addr) {
    asm volatile("ldmatrix.sync.aligned.m8n8.x4.trans.shared.b16 {%0,%1,%2,%3}, [%4];"
                 : "=r"(r[0]), "=r"(r[1]), "=r"(r[2]), "=r"(r[3]) : "r"(addr));
}

// packed half2 2^x (one MUFU op for two values)
__device__ __forceinline__ uint32_t h2exp2_(uint32_t x) {
    uint32_t r;
    asm("ex2.approx.f16x2 %0, %1;" : "=r"(r) : "r"(x));
    return r;
}

__device__ __forceinline__ void cp_async16(uint32_t dst, const void* src) {
    asm volatile("cp.async.cg.shared.global [%0], [%1], 16;"
                 :: "r"(dst), "l"(src));
}
#define CP_COMMIT()  asm volatile("cp.async.commit_group;" ::: "memory")
#define CP_WAIT(N)   asm volatile("cp.async.wait_group %0;" :: "n"(N) : "memory")

// ---------------------------------------------------------------------------
// pre-rounding pass: dst = fp16(src), up to 7 tensors per launch (grid.z)
// ---------------------------------------------------------------------------
struct RoundArgs {
    const float* src[7];
    __half*      dst[7];
    int          n4[7];     // number of float4 elements
};

__global__ __launch_bounds__(256) void round_f16(RoundArgs ra) {
    const int z = blockIdx.z;
    const int i = blockIdx.x * 256 + threadIdx.x;
    if (i >= ra.n4[z]) return;
    float4 v = ((const float4*)ra.src[z])[i];
    __half2 h0 = __floats2half2_rn(v.x, v.y);
    __half2 h1 = __floats2half2_rn(v.z, v.w);
    uint2 u;
    u.x = *(uint32_t*)&h0;
    u.y = *(uint32_t*)&h1;
    ((uint2*)ra.dst[z])[i] = u;
}

// ---------------------------------------------------------------------------
// Pipelined TN GEMM (fp16 HMMA):  C[M,N] = A[M,K] * W[N,K]^T + bias[N]
// CTA 128x128 with FOUR warps (128 threads), warp tile 64x64 (2x2 grid).
// K-tile 64, 3-stage cp.async ring, m16n8k16 HMMA. (byte-identical to R13)
// Output modes: 0 = fp16 to Ch (Q-proj), 1 = permuted fp32 into new_kv
// (K/V proj land directly in d_out), 2 = plain fp32 (O-proj).
// ---------------------------------------------------------------------------
#define NST        3
#define TILE_B     16384                 // 128 rows * 128 bytes
#define GEMM_SMEM  (2 * NST * TILE_B + 1024)
#define NKT        (D_MODEL / 64)        // 32 k-tiles

struct ProjArgs {
    const __half* A[3];
    const __half* W[3];
    const float*  Bias[3];
    float*        C[3];
    __half*       Ch[3];
    int           mode[3];
};

__global__ __launch_bounds__(128, 2) void gemm_tc(ProjArgs args) {
    extern __shared__ char dyn_smem[];
    char* db = (char*)(((uintptr_t)dyn_smem + 1023) & ~(uintptr_t)1023);
    const uint32_t db_u = smem_u32(db);

    const int z = blockIdx.z;
    const __half* __restrict__ A    = args.A[z];
    const __half* __restrict__ W    = args.W[z];
    const float*  __restrict__ bias = args.Bias[z];
    float* __restrict__        C    = args.C[z];
    __half* __restrict__       Ch   = args.Ch[z];
    const int mode = args.mode[z];

    const int tid  = threadIdx.x;
    const int lane = tid & 31;
    const int w    = tid >> 5;     // 0..3
    const int wm   = w >> 1;       // 0..1
    const int wn   = w & 1;        // 0..1
    const int n0   = blockIdx.x * 128;
    const int m0   = blockIdx.y * 128;

    const __half* Ag = A + (size_t)m0 * D_MODEL;
    const __half* Wg = W + (size_t)n0 * D_MODEL;

    // per-thread load geometry: 8 chunks A + 8 chunks B per stage (128 thr)
    uint32_t swoff[8];
    size_t   gofs[8];
#pragma unroll
    for (int rep = 0; rep < 8; rep++) {
        const int g = rep * 128 + tid;          // 0..1023
        const int r = g >> 3;                   // row 0..127
        const int i = g & 7;                    // 16B chunk
        gofs[rep]  = (size_t)r * D_MODEL + i * 8;
        swoff[rep] = (uint32_t)((r * 128 + i * 16) ^ ((r & 7) << 4));
    }

    float acc[4][8][4];
#pragma unroll
    for (int i = 0; i < 4; i++)
#pragma unroll
        for (int j = 0; j < 8; j++)
#pragma unroll
            for (int k = 0; k < 4; k++) acc[i][j][k] = 0.f;

    auto issue = [&](int ks) {
        const int slot = ks % NST;
        const int kc   = ks * 64;
        const uint32_t da  = db_u + slot * TILE_B;
        const uint32_t dbb = db_u + NST * TILE_B + slot * TILE_B;
#pragma unroll
        for (int rep = 0; rep < 8; rep++)
            cp_async16(da + swoff[rep], Ag + gofs[rep] + kc);
#pragma unroll
        for (int rep = 0; rep < 8; rep++)
            cp_async16(dbb + swoff[rep], Wg + gofs[rep] + kc);
        CP_COMMIT();
    };

    issue(0);
    issue(1);

    const int m_ = lane >> 3;
    const int rr = lane & 7;
    const int a_row_base = wm * 64 + (m_ & 1) * 8 + rr;   // + mf*16
    const int b_row_base = wn * 64 + (m_ & 1) * 8 + rr;   // + nf2*16
    const int k_half     = (m_ >> 1) * 16;

#pragma unroll 1
    for (int kt = 0; kt < NKT; kt++) {
        if (kt < NKT - 2) { CP_WAIT(1); } else { CP_WAIT(0); }
        __syncthreads();
        if (kt + 2 < NKT) issue(kt + 2);

        const int slot = kt % NST;
        const uint32_t da  = db_u + slot * TILE_B;
        const uint32_t dbb = db_u + NST * TILE_B + slot * TILE_B;

#pragma unroll
        for (int ks = 0; ks < 4; ks++) {
            const int kb = ks * 32 + k_half;
            uint32_t a[4][4], b[8][2];
#pragma unroll
            for (int mf = 0; mf < 4; mf++) {
                const int row = a_row_base + mf * 16;
                const uint32_t off = (uint32_t)((row * 128 + kb) ^ ((row & 7) << 4));
                ldsm_x4(a[mf], da + off);
            }
#pragma unroll
            for (int nf2 = 0; nf2 < 4; nf2++) {
                const int row = b_row_base + nf2 * 16;
                const uint32_t off = (uint32_t)((row * 128 + kb) ^ ((row & 7) << 4));
                uint32_t t[4];
                ldsm_x4(t, dbb + off);
                b[nf2 * 2][0]     = t[0]; b[nf2 * 2][1]     = t[2];
                b[nf2 * 2 + 1][0] = t[1]; b[nf2 * 2 + 1][1] = t[3];
            }
#pragma unroll
            for (int mf = 0; mf < 4; mf++)
#pragma unroll
                for (int nf = 0; nf < 8; nf++)
                    mma_f16(acc[mf][nf], a[mf], b[nf]);
        }
    }

    // epilogue (per mode)
#pragma unroll
    for (int mf = 0; mf < 4; mf++) {
#pragma unroll
        for (int nf = 0; nf < 8; nf++) {
            const int row = m0 + wm * 64 + mf * 16 + (lane >> 2);
            const int col = n0 + wn * 64 + nf * 8 + (lane & 3) * 2;
            const float b0 = bias[col], b1 = bias[col + 1];
            const float x0 = acc[mf][nf][0] + b0, x1 = acc[mf][nf][1] + b1;
            const float y0 = acc[mf][nf][2] + b0, y1 = acc[mf][nf][3] + b1;
            if (mode == 0) {
                __half2 h0 = __floats2half2_rn(x0, x1);
                __half2 h1 = __floats2half2_rn(y0, y1);
                *(__half2*)&Ch[(size_t)row * D_MODEL + col]       = h0;
                *(__half2*)&Ch[(size_t)(row + 8) * D_MODEL + col] = h1;
            } else if (mode == 1) {
                // direct write into new_k/new_v (proj half): t' = 1024 + t
                const int h  = col >> 7, d = col & 127;
#pragma unroll
                for (int rep = 0; rep < 2; rep++) {
                    const int rw = row + rep * 8;
                    const int bb = rw >> 10, t = rw & 1023;
                    const int j  = h * 128 + 64 + (t >> 4);
                    const int c  = (t & 15) * 128 + d;
                    float2 v = rep ? make_float2(y0, y1) : make_float2(x0, x1);
                    *(float2*)&C[((size_t)bb * 2048 + j) * 2048 + c] = v;
                }
            } else {
                *(float2*)&C[(size_t)row * D_MODEL + col]       = make_float2(x0, x1);
                *(float2*)&C[(size_t)(row + 8) * D_MODEL + col] = make_float2(y0, y1);
            }
        }
    }
}

// ---------------------------------------------------------------------------
// fp16 flash attention over the cache only (mask tril(TQ,total) => cache half).
// 128 threads (4 warps), 64 q-rows/CTA, 64 kv/tile, fused K+V commit groups,
// single CP_WAIT + 2 barriers per iteration; P in registers; l via ones-column
// tensor-core MMA; P pairs via ex2.approx.f16x2.
// R15: S=QK^T uses f16-ACCUMULATE HMMA (scores |s|<~30, fp16-safe; promoted
// to f32 once before masking/softmax). Probes the 2x f16-acc rate hypothesis.
// SMEM: Q 16K | K0 K1 32K | V0 V1 32K = 80K, 2 CTA/SM.
// qi reversed vs blockIdx.x: heavy (long) CTAs launch first -> better tail.
// ---------------------------------------------------------------------------
#define QOFF 0
#define KOFF 16384
#define VOFF (KOFF + 2 * 16384)
#define ATT_SMEM (VOFF + 2 * 16384)   // 81920

__global__ __launch_bounds__(128, 2) void attn_kernel(
    const __half* __restrict__ gQ,
    const __half* __restrict__ hK,
    const __half* __restrict__ hV,
    __half* __restrict__ gO)
{
    extern __shared__ char smc[];
    const uint32_t sb = smem_u32(smc);
    const int tid = threadIdx.x, lane = tid & 31, w = tid >> 5;
    const int qi = (int)gridDim.x - 1 - blockIdx.x;   // heavy tiles first
    const int h = blockIdx.y, b = blockIdx.z;
    const int q0 = qi * 64;

    const __half* Qg = gQ + ((size_t)b * TQ + q0) * D_MODEL + h * HEAD_DIM;
    const __half* Kg = hK + (size_t)b * CACHE_LEN * D_MODEL + h * HEAD_DIM;
    const __half* Vg = hV + (size_t)b * CACHE_LEN * D_MODEL + h * HEAD_DIM;

    // Q tile 64x128 halves -> swizzled smem (rows 256B)
#pragma unroll
    for (int rep = 0; rep < 8; rep++) {
        const int g = rep * 128 + tid;
        const int r = g >> 4, i = g & 15;
        uint4 v = *(const uint4*)(Qg + (size_t)r * D_MODEL + i * 8);
        *(uint4*)(smc + QOFF + ((r * 256 + i * 16) ^ ((r & 7) << 4))) = v;
    }

    // one commit group per kv-tile: K chunks + V chunks together
    auto issueKV = [&](int kt) {
#pragma unroll
        for (int rep = 0; rep < 8; rep++) {
            const int g = rep * 128 + tid;
            const int r = g >> 4, i = g & 15;
            const uint32_t so = (uint32_t)((r * 256 + i * 16) ^ ((r & 7) << 4));
            cp_async16(sb + KOFF + (kt & 1) * 16384 + so,
                       Kg + (size_t)(kt * 64 + r) * D_MODEL + i * 8);
            cp_async16(sb + VOFF + (kt & 1) * 16384 + so,
                       Vg + (size_t)(kt * 64 + r) * D_MODEL + i * 8);
        }
        CP_COMMIT();
    };

    issueKV(0);
    if (qi >= 1) issueKV(1); else CP_COMMIT();

    float acc_o[16][4];
#pragma unroll
    for (int i = 0; i < 16; i++)
#pragma unroll
        for (int j = 0; j < 4; j++) acc_o[i][j] = 0.f;
    float acc_l[4] = {0.f, 0.f, 0.f, 0.f};   // ones-column row-sum accumulator
    float mrow[2] = {-1e30f, -1e30f};        // running max of UNSCALED scores
    // exp(sc*(s-m)) == exp2f((s-m)*C2), C2 = (1/sqrt(128))*log2(e)
    const float C2 = (float)(0.08838834764831845 * 1.4426950408889634);

    // B-frag of all-ones in column 0 (col = lane>>2): lanes 0..3 hold 1.0h pairs
    const uint32_t b_ones = ((lane >> 2) == 0) ? 0x3C003C00u : 0u;
    uint32_t bO[2] = { b_ones, b_ones };

    const int m_ = lane >> 3, rr = lane & 7;
    const int kh    = (m_ >> 1) * 16;
    const int a_row = w * 16 + (m_ & 1) * 8 + rr;

    for (int kt = 0; kt <= qi; kt++) {
        CP_WAIT(1);            // KV(kt) landed (groups complete in order)
        __syncthreads();       // visible to all warps (covers Q on kt=0)

        const uint32_t kbase = sb + KOFF + (kt & 1) * 16384;
        uint32_t sacc[8][2];   // fp16 S accumulators (2x half2 per frag)
#pragma unroll
        for (int i = 0; i < 8; i++) { sacc[i][0] = 0u; sacc[i][1] = 0u; }

#pragma unroll
        for (int ks = 0; ks < 8; ks++) {            // 8 x k16 over headdim 128
            const int colb = ks * 32 + kh;
            uint32_t a[4];
            ldsm_x4(a, sb + QOFF + ((a_row * 256 + colb) ^ ((a_row & 7) << 4)));
            uint32_t bfr[8][2];
#pragma unroll
            for (int nf2 = 0; nf2 < 4; nf2++) {
                const int row = nf2 * 16 + (m_ & 1) * 8 + rr;   // kv rows 0..63
                uint32_t t[4];
                ldsm_x4(t, kbase + ((row * 256 + colb) ^ ((row & 7) << 4)));
                bfr[nf2 * 2][0]     = t[0]; bfr[nf2 * 2][1]     = t[2];
                bfr[nf2 * 2 + 1][0] = t[1]; bfr[nf2 * 2 + 1][1] = t[3];
            }
#pragma unroll
            for (int nf = 0; nf < 8; nf++) mma_f16acc(sacc[nf], a, bfr[nf]);
        }

        // promote fp16 scores to fp32 once
        float accs[8][4];
#pragma unroll
        for (int nf = 0; nf < 8; nf++) {
            float2 f0 = __half22float2(*(__half2*)&sacc[nf][0]);
            float2 f1 = __half22float2(*(__half2*)&sacc[nf][1]);
            accs[nf][0] = f0.x; accs[nf][1] = f0.y;
            accs[nf][2] = f1.x; accs[nf][3] = f1.y;
        }

        // causal mask (diagonal tile only) on UNSCALED scores
        if (kt == qi) {
#pragma unroll
            for (int nf = 0; nf < 8; nf++)
#pragma unroll
                for (int r = 0; r < 2; r++)
#pragma unroll
                    for (int j = 0; j < 2; j++) {
                        const int cl = nf * 8 + (lane & 3) * 2 + j;
                        const int rl = w * 16 + (lane >> 2) + r * 8;
                        if (cl > rl) accs[nf][r * 2 + j] = -1e30f;
                    }
        }

        // online softmax (scale folded into exp2; P pairs via ex2.f16x2)
        uint32_t ph[8][2];
#pragma unroll
        for (int r = 0; r < 2; r++) {
            float vmax = -1e30f;
#pragma unroll
            for (int nf = 0; nf < 8; nf++) {
                vmax = fmaxf(vmax, accs[nf][r * 2]);
                vmax = fmaxf(vmax, accs[nf][r * 2 + 1]);
            }
            vmax = fmaxf(vmax, __shfl_xor_sync(0xffffffffu, vmax, 1));
            vmax = fmaxf(vmax, __shfl_xor_sync(0xffffffffu, vmax, 2));
            const float mnew = fmaxf(mrow[r], vmax);
#pragma unroll
            for (int nf = 0; nf < 8; nf++) {
                __half2 e = __floats2half2_rn((accs[nf][r * 2]     - mnew) * C2,
                                              (accs[nf][r * 2 + 1] - mnew) * C2);
                ph[nf][r] = h2exp2_(*(uint32_t*)&e);
            }
            const float alpha = exp2f((mrow[r] - mnew) * C2);
            mrow[r] = mnew;
            acc_l[r * 2]     *= alpha;
            acc_l[r * 2 + 1] *= alpha;
#pragma unroll
            for (int nf = 0; nf < 16; nf++) {
                acc_o[nf][r * 2]     *= alpha;
                acc_o[nf][r * 2 + 1] *= alpha;
            }
        }

        // O += P * V ; l += P * 1  (V arrived with K; P A-frags from registers)
        const uint32_t vbase = sb + VOFF + (kt & 1) * 16384;
        const int vr_lane = ((lane >> 3) & 1) * 8 + (lane & 7);
        const int vc_lane = (lane >> 4) * 16;
#pragma unroll
        for (int ks = 0; ks < 4; ks++) {            // 4 x k16 over 64 kv
            uint32_t aP[4];
            aP[0] = ph[2 * ks][0];
            aP[1] = ph[2 * ks][1];
            aP[2] = ph[2 * ks + 1][0];
            aP[3] = ph[2 * ks + 1][1];
            mma_f16(acc_l, aP, bO);                 // row-sum into col 0
#pragma unroll
            for (int dg = 0; dg < 8; dg++) {        // 16 halves of headdim each
                const int vrow = ks * 16 + vr_lane;
                const int vcol = dg * 32 + vc_lane;
                uint32_t t[4];
                ldsm_x4t(t, vbase + ((vrow * 256 + vcol) ^ ((vrow & 7) << 4)));
                uint32_t b0[2] = { t[0], t[1] };
                uint32_t b1[2] = { t[2], t[3] };
                mma_f16(acc_o[dg * 2],     aP, b0);
                mma_f16(acc_o[dg * 2 + 1], aP, b1);
            }
        }

        __syncthreads();       // all warps done reading K(kt)/V(kt)
        if (kt + 2 <= qi) issueKV(kt + 2); else CP_COMMIT();
    }

    // l lives in col 0 (lanes with lane%4==0); broadcast across each quad
    const int qlead = lane & ~3;
    const float l0 = __shfl_sync(0xffffffffu, acc_l[0], qlead);
    const float l1 = __shfl_sync(0xffffffffu, acc_l[2], qlead);
    const float inv0 = 1.f / l0;
    const float inv1 = 1.f / l1;

    // normalize + write fp16
#pragma unroll
    for (int nf = 0; nf < 16; nf++)
#pragma unroll
        for (int r = 0; r < 2; r++) {
            const int row = q0 + w * 16 + (lane >> 2) + r * 8;
            const int col = h * HEAD_DIM + nf * 8 + (lane & 3) * 2;
            const float inv = r ? inv1 : inv0;
            __half2 hv = __floats2half2_rn(acc_o[nf][r * 2] * inv,
                                           acc_o[nf][r * 2 + 1] * inv);
            *(__half2*)&gO[((size_t)b * TQ + row) * D_MODEL + col] = hv;
        }
}

// ---------------------------------------------------------------------------
// cache pass, fused: permuted fp32 cache half of new_k/new_v into d_out AND
// fp16 rounding of the caches for attention (single read of each cache).
// grid.z: 0 -> K, 1 -> V. 2097152 float4 per tensor.
// ---------------------------------------------------------------------------
__global__ __launch_bounds__(256) void copy_cache_kv(
    const float* __restrict__ cacheK,
    const float* __restrict__ cacheV,
    float* __restrict__ dstK,
    float* __restrict__ dstV,
    __half* __restrict__ hcK,
    __half* __restrict__ hcV)
{
    const int i = blockIdx.x * 256 + threadIdx.x;
    const int b   = i >> 19;            // 524288 float4 per batch
    const int rem = i & 524287;
    const int jj  = rem >> 9;           // 0..1023 (h*64 + cache row)
    const int c   = (rem & 511) * 4;
    const int h   = jj >> 6;
    const int j   = h * 128 + (jj & 63);
    const int t   = (jj & 63) * 16 + (c >> 7);
    const int d   = c & 127;

    const float* cache = blockIdx.z ? cacheV : cacheK;
    float*       dst   = blockIdx.z ? dstV   : dstK;
    __half*      hc    = blockIdx.z ? hcV    : hcK;

    const size_t src_off = ((size_t)b * CACHE_LEN + t) * D_MODEL + h * HEAD_DIM + d;
    float4 v = *(const float4*)&cache[src_off];
    *(float4*)&dst[((size_t)b * 2048 + j) * D_MODEL + c] = v;

    __half2 h0 = __floats2half2_rn(v.x, v.y);
    __half2 h1 = __floats2half2_rn(v.z, v.w);
    uint2 u;
    u.x = *(uint32_t*)&h0;
    u.y = *(uint32_t*)&h1;
    *(uint2*)&hc[src_off] = u;
}

// ---------------------------------------------------------------------------
// launch — R13 two-branch DAG (the 500.5us config; R14's 3-stream variant was
// neutral-negative and is reverted):
//   s2 (t=0):   cache pass (->evC) -> round(k,v,Wk,Wv) -> K/V-proj (->evK)
//   s0:         round(q,Wq,Wo) -> Q-proj -> [evC] attn -> O-proj -> [evK]
// ---------------------------------------------------------------------------
extern "C" void kernel_launch(void* const* d_in, const int* in_sizes, int n_in,
                              void* d_out, int out_size)
{
    const float* query   = (const float*)d_in[0];
    const float* key     = (const float*)d_in[1];
    const float* value   = (const float*)d_in[2];
    const float* cacheK  = (const float*)d_in[3];
    const float* cacheV  = (const float*)d_in[4];
    const float* Wq      = (const float*)d_in[5];
    const float* bq      = (const float*)d_in[6];
    const float* Wk      = (const float*)d_in[7];
    const float* bk      = (const float*)d_in[8];
    const float* Wv      = (const float*)d_in[9];
    const float* bv      = (const float*)d_in[10];
    const float* Wo      = (const float*)d_in[11];
    const float* bo      = (const float*)d_in[12];
    float* out = (float*)d_out;

    __half *phQ, *pO, *phq, *phk, *phv, *phWq, *phWk, *phWv, *phWo, *phck, *phcv;
    cudaGetSymbolAddress((void**)&phQ, g_hQ);
    cudaGetSymbolAddress((void**)&pO, g_O);
    cudaGetSymbolAddress((void**)&phq, g_hq);
    cudaGetSymbolAddress((void**)&phk, g_hk);
    cudaGetSymbolAddress((void**)&phv, g_hv);
    cudaGetSymbolAddress((void**)&phWq, g_hWq);
    cudaGetSymbolAddress((void**)&phWk, g_hWk);
    cudaGetSymbolAddress((void**)&phWv, g_hWv);
    cudaGetSymbolAddress((void**)&phWo, g_hWo);
    cudaGetSymbolAddress((void**)&phck, g_hck);
    cudaGetSymbolAddress((void**)&phcv, g_hcv);

    // one-time stream/event creation (resources only; identical work per call)
    static cudaStream_t s2 = nullptr;
    static cudaEvent_t  evF = nullptr, evC = nullptr, evK = nullptr;
    if (s2 == nullptr) {
        cudaStreamCreateWithFlags(&s2, cudaStreamNonBlocking);
        cudaEventCreateWithFlags(&evF, cudaEventDisableTiming);
        cudaEventCreateWithFlags(&evC, cudaEventDisableTiming);
        cudaEventCreateWithFlags(&evK, cudaEventDisableTiming);
    }

    cudaFuncSetAttribute(gemm_tc, cudaFuncAttributeMaxDynamicSharedMemorySize,
                         GEMM_SMEM);
    cudaFuncSetAttribute(attn_kernel, cudaFuncAttributeMaxDynamicSharedMemorySize,
                         ATT_SMEM);

    const int NA = M_ROWS * D_MODEL / 4;     // 2097152 float4
    const int NW = D_MODEL * D_MODEL / 4;    // 1048576 float4

    // fork s2 at t=0 (its first kernels have no s0 dependencies)
    cudaEventRecord(evF, 0);
    cudaStreamWaitEvent(s2, evF, 0);

    // ---- s2 branch ----
    copy_cache_kv<<<dim3(2097152 / 256, 1, 2), 256, 0, s2>>>(
        cacheK, cacheV, out + 8388608, out + 25165824, phck, phcv);
    cudaEventRecord(evC, s2);

    RoundArgs rb;
    rb.src[0] = key;   rb.dst[0] = phk;  rb.n4[0] = NA;
    rb.src[1] = value; rb.dst[1] = phv;  rb.n4[1] = NA;
    rb.src[2] = Wk;    rb.dst[2] = phWk; rb.n4[2] = NW;
    rb.src[3] = Wv;    rb.dst[3] = phWv; rb.n4[3] = NW;
    for (int s = 4; s < 7; s++) { rb.src[s] = Wv; rb.dst[s] = phWv; rb.n4[s] = 0; }
    round_f16<<<dim3(NA / 256, 1, 4), 256, 0, s2>>>(rb);

    ProjArgs pkv;
    pkv.A[0] = phk; pkv.W[0] = phWk; pkv.Bias[0] = bk;
    pkv.C[0] = out + 8388608;  pkv.Ch[0] = nullptr; pkv.mode[0] = 1;
    pkv.A[1] = phv; pkv.W[1] = phWv; pkv.Bias[1] = bv;
    pkv.C[1] = out + 25165824; pkv.Ch[1] = nullptr; pkv.mode[1] = 1;
    pkv.A[2] = pkv.A[0]; pkv.W[2] = pkv.W[0]; pkv.Bias[2] = pkv.Bias[0];
    pkv.C[2] = pkv.C[0]; pkv.Ch[2] = nullptr; pkv.mode[2] = 1;
    gemm_tc<<<dim3(D_MODEL / 128, M_ROWS / 128, 2), 128, GEMM_SMEM, s2>>>(pkv);
    cudaEventRecord(evK, s2);

    // ---- s0 branch ----
    RoundArgs raA;
    raA.src[0] = query; raA.dst[0] = phq;  raA.n4[0] = NA;
    raA.src[1] = Wq;    raA.dst[1] = phWq; raA.n4[1] = NW;
    raA.src[2] = Wo;    raA.dst[2] = phWo; raA.n4[2] = NW;
    for (int s = 3; s < 7; s++) { raA.src[s] = Wo; raA.dst[s] = phWo; raA.n4[s] = 0; }
    round_f16<<<dim3(NA / 256, 1, 3), 256>>>(raA);

    ProjArgs pq;
    pq.A[0] = phq; pq.W[0] = phWq; pq.Bias[0] = bq;
    pq.C[0] = nullptr; pq.Ch[0] = phQ; pq.mode[0] = 0;
    pq.A[1] = pq.A[0]; pq.W[1] = pq.W[0]; pq.Bias[1] = pq.Bias[0];
    pq.C[1] = nullptr; pq.Ch[1] = phQ; pq.mode[1] = 0;
    pq.A[2] = pq.A[0]; pq.W[2] = pq.W[0]; pq.Bias[2] = pq.Bias[0];
    pq.C[2] = nullptr; pq.Ch[2] = phQ; pq.mode[2] = 0;
    gemm_tc<<<dim3(D_MODEL / 128, M_ROWS / 128, 1), 128, GEMM_SMEM>>>(pq);

    // attention needs the fp16 caches from s2's cache pass
    cudaStreamWaitEvent(0, evC, 0);
    attn_kernel<<<dim3(TQ / 64, NUM_HEADS, BATCH), 128, ATT_SMEM>>>(
        phQ, phck, phcv, pO);

    // O-projection -> out[0 .. 8388608)  (co-runs with K/V-proj tail)
    ProjArgs po;
    po.A[0] = pO; po.W[0] = phWo; po.Bias[0] = bo;
    po.C[0] = out; po.Ch[0] = nullptr; po.mode[0] = 2;
    po.A[1] = po.A[0]; po.W[1] = po.W[0]; po.Bias[1] = po.Bias[0];
    po.C[1] = po.C[0]; po.Ch[1] = nullptr; po.mode[1] = 2;
    po.A[2] = po.A[0]; po.W[2] = po.W[0]; po.Bias[2] = po.Bias[0];
    po.C[2] = po.C[0]; po.Ch[2] = nullptr; po.mode[2] = 2;
    gemm_tc<<<dim3(D_MODEL / 128, M_ROWS / 128, 1), 128, GEMM_SMEM>>>(po);

    // join
    cudaStreamWaitEvent(0, evK, 0);
}